// round 6
// baseline (speedup 1.0000x reference)
#include <cuda_runtime.h>

#define M_SLOTS 16
#define KEY_DIM 1024
#define ITEMS   4            // float4 per thread
#define TPB     256
#define TILE_F4 (TPB * ITEMS)   // 1024 float4 per block tile

// ---------------------------------------------------------------------------
// Fully fused kernel:
//   Phase A: every block redundantly computes cosine-sim + softmax weights
//            (68KB of L2-resident input; 8 warps x 2 slots each).
//   Phase B: weighted sum over 16 slots, 4 float4 per thread.
// One launch, no inter-kernel dependency.
// ---------------------------------------------------------------------------
__global__ void __launch_bounds__(TPB) fused_kernel(
        const float*  __restrict__ task_emb,
        const float*  __restrict__ K_memory,
        const float4* __restrict__ V0,
        const float4* __restrict__ V1,
        float4*       __restrict__ out,
        int nv4_0, int nv4_1) {
    __shared__ float s_w[M_SLOTS];

    const int tid  = threadIdx.x;
    const int warp = tid >> 5;          // 0..7
    const int lane = tid & 31;

    // ---------------- Phase A: weights (redundant per block) ----------------
    {
        const int sa = 2 * warp;        // slots handled by this warp
        const int sb = 2 * warp + 1;
        const float4* t4 = (const float4*)task_emb;                  // 256 f4
        const float4* ka = (const float4*)(K_memory + sa * KEY_DIM);
        const float4* kb = (const float4*)(K_memory + sb * KEY_DIM);

        float dota = 0.f, dotb = 0.f, kka = 0.f, kkb = 0.f, tt = 0.f;
        #pragma unroll
        for (int j = 0; j < 8; j++) {
            float4 t = t4[lane + 32 * j];
            float4 a = ka[lane + 32 * j];
            float4 b = kb[lane + 32 * j];
            dota = fmaf(t.x, a.x, dota); dota = fmaf(t.y, a.y, dota);
            dota = fmaf(t.z, a.z, dota); dota = fmaf(t.w, a.w, dota);
            dotb = fmaf(t.x, b.x, dotb); dotb = fmaf(t.y, b.y, dotb);
            dotb = fmaf(t.z, b.z, dotb); dotb = fmaf(t.w, b.w, dotb);
            kka  = fmaf(a.x, a.x, kka);  kka  = fmaf(a.y, a.y, kka);
            kka  = fmaf(a.z, a.z, kka);  kka  = fmaf(a.w, a.w, kka);
            kkb  = fmaf(b.x, b.x, kkb);  kkb  = fmaf(b.y, b.y, kkb);
            kkb  = fmaf(b.z, b.z, kkb);  kkb  = fmaf(b.w, b.w, kkb);
            tt   = fmaf(t.x, t.x, tt);   tt   = fmaf(t.y, t.y, tt);
            tt   = fmaf(t.z, t.z, tt);   tt   = fmaf(t.w, t.w, tt);
        }
        #pragma unroll
        for (int off = 16; off > 0; off >>= 1) {
            dota += __shfl_down_sync(0xffffffffu, dota, off);
            dotb += __shfl_down_sync(0xffffffffu, dotb, off);
            kka  += __shfl_down_sync(0xffffffffu, kka,  off);
            kkb  += __shfl_down_sync(0xffffffffu, kkb,  off);
            tt   += __shfl_down_sync(0xffffffffu, tt,   off);
        }
        if (lane == 0) {
            float n1 = sqrtf(tt);
            s_w[sa] = dota / fmaxf(n1 * sqrtf(kka), 1e-6f);
            s_w[sb] = dotb / fmaxf(n1 * sqrtf(kkb), 1e-6f);
        }
    }
    __syncthreads();

    if (tid == 0) {
        float c[M_SLOTS];
        float mx = -1e30f;
        #pragma unroll
        for (int m = 0; m < M_SLOTS; m++) { c[m] = s_w[m]; mx = fmaxf(mx, c[m]); }
        float sum = 0.f;
        #pragma unroll
        for (int m = 0; m < M_SLOTS; m++) { c[m] = __expf(c[m] - mx); sum += c[m]; }
        float inv = 1.0f / sum;
        #pragma unroll
        for (int m = 0; m < M_SLOTS; m++) s_w[m] = c[m] * inv;
    }
    __syncthreads();

    // ---------------- Phase B: weighted sum, 4 float4 per thread ------------
    const int tile0 = blockIdx.x * TILE_F4;     // block tiles never straddle V0/V1
    const float4* __restrict__ V;
    size_t stride;
    int base;
    if (tile0 < nv4_0) { V = V0; base = tile0;          stride = (size_t)nv4_0; }
    else               { V = V1; base = tile0 - nv4_0;  stride = (size_t)nv4_1; }

    float4 acc0 = make_float4(0.f, 0.f, 0.f, 0.f);
    float4 acc1 = acc0, acc2 = acc0, acc3 = acc0;

    #pragma unroll
    for (int m = 0; m < M_SLOTS; m++) {
        const float wm = s_w[m];
        const float4* p = V + (size_t)m * stride + (size_t)base + tid;
        float4 v0 = p[0 * TPB];
        float4 v1 = p[1 * TPB];
        float4 v2 = p[2 * TPB];
        float4 v3 = p[3 * TPB];
        acc0.x = fmaf(wm, v0.x, acc0.x); acc0.y = fmaf(wm, v0.y, acc0.y);
        acc0.z = fmaf(wm, v0.z, acc0.z); acc0.w = fmaf(wm, v0.w, acc0.w);
        acc1.x = fmaf(wm, v1.x, acc1.x); acc1.y = fmaf(wm, v1.y, acc1.y);
        acc1.z = fmaf(wm, v1.z, acc1.z); acc1.w = fmaf(wm, v1.w, acc1.w);
        acc2.x = fmaf(wm, v2.x, acc2.x); acc2.y = fmaf(wm, v2.y, acc2.y);
        acc2.z = fmaf(wm, v2.z, acc2.z); acc2.w = fmaf(wm, v2.w, acc2.w);
        acc3.x = fmaf(wm, v3.x, acc3.x); acc3.y = fmaf(wm, v3.y, acc3.y);
        acc3.z = fmaf(wm, v3.z, acc3.z); acc3.w = fmaf(wm, v3.w, acc3.w);
    }

    float4* dst = out + tile0 + tid;
    dst[0 * TPB] = acc0;
    dst[1 * TPB] = acc1;
    dst[2 * TPB] = acc2;
    dst[3 * TPB] = acc3;
}

// ---------------------------------------------------------------------------
// Launch contract
// Inputs (metadata order): task_emb [1,1024] f32, K_memory [16,1024] f32,
//                          V0 [16,1024,1024] f32, V1 [16,1024,4096] f32
// Output: rec0 [1024,1024] f32 followed by rec1 [1024,4096] f32
// ---------------------------------------------------------------------------
extern "C" void kernel_launch(void* const* d_in, const int* in_sizes, int n_in,
                              void* d_out, int out_size) {
    const float* task_emb = (const float*)d_in[0];
    const float* K_memory = (const float*)d_in[1];
    const float* V0       = (const float*)d_in[2];
    const float* V1       = (const float*)d_in[3];
    float* out = (float*)d_out;

    const int n0 = in_sizes[2] / M_SLOTS;   // 1024*1024
    const int n1 = in_sizes[3] / M_SLOTS;   // 1024*4096
    const int nv4_0 = n0 / 4;               // 262144  (= 256 tiles of 1024)
    const int nv4_1 = n1 / 4;               // 1048576 (= 1024 tiles)
    const int total = nv4_0 + nv4_1;
    const int blocks = (total + TILE_F4 - 1) / TILE_F4;   // 1280

    fused_kernel<<<blocks, TPB>>>(task_emb, K_memory,
                                  (const float4*)V0, (const float4*)V1,
                                  (float4*)out, nv4_0, nv4_1);
}